// round 1
// baseline (speedup 1.0000x reference)
#include <cuda_runtime.h>

#define B_SZ 16
#define N_PTS 4096
#define K_NN 20
#define CO 64
#define STAT_BLOCKS 256
#define NVALS 27

// ---------------- scratch (static device allocations, allowed) ----------------
__device__ int    g_idx[B_SZ * N_PTS * K_NN];       // 5.24 MB
__device__ double g_part[STAT_BLOCKS * NVALS];
__device__ float  g_scale[CO];
__device__ float  g_shift[CO];

// =============================================================================
// Kernel 1: per-batch brute-force KNN (top-20 smallest d = sq_n + sq_m - 2*dot)
// One query point per thread; all 4096 candidates of the batch staged in smem.
// Sorted insertion keeps ties in index order (strict <), matching jax top_k.
// =============================================================================
__global__ void knn_kernel(const float* __restrict__ x) {
    extern __shared__ float4 pts[];
    const int b = blockIdx.y;
    const float* xb = x + (size_t)b * N_PTS * 3;

    for (int i = threadIdx.x; i < N_PTS; i += blockDim.x) {
        float x0 = xb[i * 3 + 0], x1 = xb[i * 3 + 1], x2 = xb[i * 3 + 2];
        float sq = __fadd_rn(__fadd_rn(__fmul_rn(x0, x0), __fmul_rn(x1, x1)),
                             __fmul_rn(x2, x2));
        pts[i] = make_float4(x0, x1, x2, sq);
    }
    __syncthreads();

    const int q = blockIdx.x * blockDim.x + threadIdx.x;
    const float4 qp = pts[q];

    float hd[K_NN];
    int   hi[K_NN];
#pragma unroll
    for (int j = 0; j < K_NN; j++) { hd[j] = 3.402823466e38f; hi[j] = 0; }

    for (int m = 0; m < N_PTS; m++) {
        float4 p = pts[m];
        float t = __fadd_rn(__fadd_rn(__fmul_rn(qp.x, p.x), __fmul_rn(qp.y, p.y)),
                            __fmul_rn(qp.z, p.z));
        float s = __fadd_rn(qp.w, p.w);
        float d = __fsub_rn(s, __fmul_rn(2.0f, t));
        if (d < hd[K_NN - 1]) {
            hd[K_NN - 1] = d;
            hi[K_NN - 1] = m;
#pragma unroll
            for (int j = K_NN - 1; j > 0; --j) {
                if (hd[j] < hd[j - 1]) {
                    float tf = hd[j]; hd[j] = hd[j - 1]; hd[j - 1] = tf;
                    int   ti = hi[j]; hi[j] = hi[j - 1]; hi[j - 1] = ti;
                }
            }
        }
    }

    int base = (b * N_PTS + q) * K_NN;
#pragma unroll
    for (int j = 0; j < K_NN; j++) g_idx[base + j] = hi[j];
}

// =============================================================================
// Kernel 2: fp64 moment accumulation for the global BatchNorm statistics.
// h_c(edge) = p_c . xi + q_c . xj + b1_c   (affine in xi, xj)
// so mean/var per channel need only these 27 moments over all edges:
//   [0..2]  Px   = sum_points x           (Si = K*Px)
//   [3..8]  Pxx  = sum_points x x^T (sym) (Mii = K*Pxx)
//   [9..11] Sj   = sum_edges xj
//   [12..17]Mjj  = sum_edges xj xj^T (sym)
//   [18..26]Mij  = sum_edges xi xj^T (3x3, row-major)
// Deterministic: block tree-reduce -> g_part, summed serially in finalize.
// =============================================================================
__global__ void stats_kernel(const float* __restrict__ x) {
    const int pt = blockIdx.x * blockDim.x + threadIdx.x;   // 0..65535
    const int b = pt >> 12;
    const int gbase = b << 12;

    const float* xr = x + (size_t)pt * 3;
    double di0 = (double)xr[0], di1 = (double)xr[1], di2 = (double)xr[2];

    double sj0 = 0, sj1 = 0, sj2 = 0;
    double jj00 = 0, jj01 = 0, jj02 = 0, jj11 = 0, jj12 = 0, jj22 = 0;
    double ij00 = 0, ij01 = 0, ij02 = 0, ij10 = 0, ij11 = 0, ij12 = 0,
           ij20 = 0, ij21 = 0, ij22 = 0;

    const int* ip = g_idx + (size_t)pt * K_NN;
#pragma unroll 4
    for (int k = 0; k < K_NN; k++) {
        int j = __ldg(ip + k);
        const float* xp = x + (size_t)(gbase + j) * 3;
        double j0 = (double)__ldg(xp + 0);
        double j1 = (double)__ldg(xp + 1);
        double j2 = (double)__ldg(xp + 2);
        sj0 += j0; sj1 += j1; sj2 += j2;
        jj00 += j0 * j0; jj01 += j0 * j1; jj02 += j0 * j2;
        jj11 += j1 * j1; jj12 += j1 * j2; jj22 += j2 * j2;
        ij00 += di0 * j0; ij01 += di0 * j1; ij02 += di0 * j2;
        ij10 += di1 * j0; ij11 += di1 * j1; ij12 += di1 * j2;
        ij20 += di2 * j0; ij21 += di2 * j1; ij22 += di2 * j2;
    }

    double vals[NVALS] = {
        di0, di1, di2,
        di0 * di0, di0 * di1, di0 * di2, di1 * di1, di1 * di2, di2 * di2,
        sj0, sj1, sj2,
        jj00, jj01, jj02, jj11, jj12, jj22,
        ij00, ij01, ij02, ij10, ij11, ij12, ij20, ij21, ij22
    };

    __shared__ double red[256];
#pragma unroll
    for (int v = 0; v < NVALS; v++) {
        red[threadIdx.x] = vals[v];
        __syncthreads();
        for (int s = 128; s > 0; s >>= 1) {
            if (threadIdx.x < s) red[threadIdx.x] += red[threadIdx.x + s];
            __syncthreads();
        }
        if (threadIdx.x == 0) g_part[blockIdx.x * NVALS + v] = red[0];
        __syncthreads();
    }
}

// =============================================================================
// Kernel 3: finalize BN stats -> per-channel scale/shift (fp64 math).
// =============================================================================
__global__ void finalize_kernel(const float* __restrict__ w1,
                                const float* __restrict__ b1,
                                const float* __restrict__ gamma,
                                const float* __restrict__ beta) {
    __shared__ double S[NVALS];
    if (threadIdx.x < NVALS) {
        double s = 0.0;
        for (int bl = 0; bl < STAT_BLOCKS; bl++) s += g_part[bl * NVALS + threadIdx.x];
        S[threadIdx.x] = s;
    }
    __syncthreads();

    const int c = threadIdx.x;              // 64 threads
    const double M = (double)B_SZ * N_PTS * K_NN;   // 1310720
    const double Kd = (double)K_NN;

    double q0 = (double)w1[3 * CO + c], q1 = (double)w1[4 * CO + c], q2 = (double)w1[5 * CO + c];
    double p0 = (double)w1[0 * CO + c] - q0;
    double p1 = (double)w1[1 * CO + c] - q1;
    double p2 = (double)w1[2 * CO + c] - q2;
    double s_ = (double)b1[c];

    double Si0 = Kd * S[0], Si1 = Kd * S[1], Si2 = Kd * S[2];
    double i00 = Kd * S[3], i01 = Kd * S[4], i02 = Kd * S[5];
    double i11 = Kd * S[6], i12 = Kd * S[7], i22 = Kd * S[8];
    double Sj0 = S[9], Sj1 = S[10], Sj2 = S[11];
    double j00 = S[12], j01 = S[13], j02 = S[14], j11 = S[15], j12 = S[16], j22 = S[17];

    double pSi = p0 * Si0 + p1 * Si1 + p2 * Si2;
    double qSj = q0 * Sj0 + q1 * Sj1 + q2 * Sj2;
    double mean = (pSi + qSj) / M + s_;

    double pMp = p0 * p0 * i00 + p1 * p1 * i11 + p2 * p2 * i22 +
                 2.0 * (p0 * p1 * i01 + p0 * p2 * i02 + p1 * p2 * i12);
    double qMq = q0 * q0 * j00 + q1 * q1 * j11 + q2 * q2 * j22 +
                 2.0 * (q0 * q1 * j01 + q0 * q2 * j02 + q1 * q2 * j12);
    double pMq = p0 * (q0 * S[18] + q1 * S[19] + q2 * S[20]) +
                 p1 * (q0 * S[21] + q1 * S[22] + q2 * S[23]) +
                 p2 * (q0 * S[24] + q1 * S[25] + q2 * S[26]);

    double sumsq = pMp + qMq + 2.0 * pMq + 2.0 * s_ * (pSi + qSj) + M * s_ * s_;
    double var = sumsq / M - mean * mean;
    double rstd = 1.0 / sqrt(var + 1e-5);

    double g = (double)gamma[c];
    g_scale[c] = (float)(g * rstd);
    g_shift[c] = (float)((double)beta[c] - mean * g * rstd);
}

// =============================================================================
// Kernel 4: fused edge-MLP + BN + ReLU + (r @ w2) + max over K.
// One warp per point: 2 output channels per lane, 20 k-accumulators in regs.
// r stored per-warp in smem transposed [c_in][k] so stage 2 uses float4 LDS.
// =============================================================================
__global__ void __launch_bounds__(256, 2)
main_kernel(const float* __restrict__ x,
            const float* __restrict__ w1,
            const float* __restrict__ b1,
            const float* __restrict__ w2,
            const float* __restrict__ b2,
            float* __restrict__ out) {
    extern __shared__ float sm[];
    float* w2s = sm;               // 64*64
    float* rt  = sm + CO * CO;     // 8 warps * 64 * 20

    for (int i = threadIdx.x; i < CO * CO; i += blockDim.x) w2s[i] = w2[i];
    __syncthreads();

    const int w = threadIdx.x >> 5;
    const int l = threadIdx.x & 31;
    const int pt = blockIdx.x * 8 + w;
    float* rw = rt + w * (CO * K_NN);

    const int ca = l, cb = l + 32;

    float w1a[6], w1b[6];
#pragma unroll
    for (int r = 0; r < 6; r++) { w1a[r] = __ldg(w1 + r * CO + ca); w1b[r] = __ldg(w1 + r * CO + cb); }
    const float b1a = __ldg(b1 + ca), b1b = __ldg(b1 + cb);
    const float sca = g_scale[ca], scb = g_scale[cb];
    const float sha = g_shift[ca], shb = g_shift[cb];

    const int b = pt >> 12;
    const int gbase = b << 12;
    const float* xr = x + (size_t)pt * 3;
    const float xi0 = __ldg(xr), xi1 = __ldg(xr + 1), xi2 = __ldg(xr + 2);
    const int* ip = g_idx + (size_t)pt * K_NN;

    // ---- stage 1: r[c][k] = relu(scale*h + shift) ----
#pragma unroll 4
    for (int k = 0; k < K_NN; k++) {
        int j = __ldg(ip + k);
        const float* xp = x + (size_t)(gbase + j) * 3;
        float d0 = __ldg(xp)     - xi0;
        float d1 = __ldg(xp + 1) - xi1;
        float d2 = __ldg(xp + 2) - xi2;

        float ha = b1a;
        ha = fmaf(xi0, w1a[0], ha); ha = fmaf(xi1, w1a[1], ha); ha = fmaf(xi2, w1a[2], ha);
        ha = fmaf(d0,  w1a[3], ha); ha = fmaf(d1,  w1a[4], ha); ha = fmaf(d2,  w1a[5], ha);
        float hb = b1b;
        hb = fmaf(xi0, w1b[0], hb); hb = fmaf(xi1, w1b[1], hb); hb = fmaf(xi2, w1b[2], hb);
        hb = fmaf(d0,  w1b[3], hb); hb = fmaf(d1,  w1b[4], hb); hb = fmaf(d2,  w1b[5], hb);

        rw[ca * K_NN + k] = fmaxf(fmaf(ha, sca, sha), 0.0f);
        rw[cb * K_NN + k] = fmaxf(fmaf(hb, scb, shb), 0.0f);
    }
    __syncwarp();

    // ---- stage 2: acc[k][cout] += r[c][k] * w2[c][cout]; then max over k ----
    float acca[K_NN], accb[K_NN];
#pragma unroll
    for (int k = 0; k < K_NN; k++) { acca[k] = 0.0f; accb[k] = 0.0f; }

#pragma unroll 4
    for (int c = 0; c < CO; c++) {
        float wa = w2s[c * CO + ca];
        float wb = w2s[c * CO + cb];
        const float4* r4 = (const float4*)(rw + c * K_NN);
#pragma unroll
        for (int t = 0; t < 5; t++) {
            float4 rv = r4[t];
            acca[4 * t + 0] = fmaf(rv.x, wa, acca[4 * t + 0]);
            acca[4 * t + 1] = fmaf(rv.y, wa, acca[4 * t + 1]);
            acca[4 * t + 2] = fmaf(rv.z, wa, acca[4 * t + 2]);
            acca[4 * t + 3] = fmaf(rv.w, wa, acca[4 * t + 3]);
            accb[4 * t + 0] = fmaf(rv.x, wb, accb[4 * t + 0]);
            accb[4 * t + 1] = fmaf(rv.y, wb, accb[4 * t + 1]);
            accb[4 * t + 2] = fmaf(rv.z, wb, accb[4 * t + 2]);
            accb[4 * t + 3] = fmaf(rv.w, wb, accb[4 * t + 3]);
        }
    }

    float ma = acca[0], mb = accb[0];
#pragma unroll
    for (int k = 1; k < K_NN; k++) { ma = fmaxf(ma, acca[k]); mb = fmaxf(mb, accb[k]); }

    out[(size_t)pt * CO + ca] = ma + __ldg(b2 + ca);
    out[(size_t)pt * CO + cb] = mb + __ldg(b2 + cb);
}

// =============================================================================
extern "C" void kernel_launch(void* const* d_in, const int* in_sizes, int n_in,
                              void* d_out, int out_size) {
    const float* x     = (const float*)d_in[0];
    // d_in[1] = batch indices (implied by layout; unused)
    const float* w1    = (const float*)d_in[2];
    const float* b1    = (const float*)d_in[3];
    const float* gamma = (const float*)d_in[4];
    const float* beta  = (const float*)d_in[5];
    const float* w2    = (const float*)d_in[6];
    const float* b2    = (const float*)d_in[7];
    float* out = (float*)d_out;

    const int knn_smem  = N_PTS * sizeof(float4);                       // 64 KB
    const int main_smem = (CO * CO + 8 * CO * K_NN) * sizeof(float);    // 56 KB

    cudaFuncSetAttribute(knn_kernel,  cudaFuncAttributeMaxDynamicSharedMemorySize, knn_smem);
    cudaFuncSetAttribute(main_kernel, cudaFuncAttributeMaxDynamicSharedMemorySize, main_smem);

    knn_kernel<<<dim3(N_PTS / 256, B_SZ), 256, knn_smem>>>(x);
    stats_kernel<<<STAT_BLOCKS, 256>>>(x);
    finalize_kernel<<<1, 64>>>(w1, b1, gamma, beta);
    main_kernel<<<(B_SZ * N_PTS) / 8, 256, main_smem>>>(x, w1, b1, w2, b2, out);
}

// round 2
// speedup vs baseline: 1.4476x; 1.4476x over previous
#include <cuda_runtime.h>

#define B_SZ 16
#define N_PTS 4096
#define K_NN 20
#define CO 64
#define STAT_BLOCKS 256
#define NVALS 27
#define BUF_SZ 24

// ---------------- scratch (static device allocations, allowed) ----------------
__device__ int    g_idx[B_SZ * N_PTS * K_NN];       // 5.24 MB
__device__ double g_part[STAT_BLOCKS * NVALS];
__device__ float  g_scale[CO];
__device__ float  g_shift[CO];

// packed f32x2 helpers (sm_100+ PTX)
__device__ __forceinline__ unsigned long long pack2(float lo, float hi) {
    unsigned long long r;
    asm("mov.b64 %0, {%1,%2};" : "=l"(r) : "f"(lo), "f"(hi));
    return r;
}
__device__ __forceinline__ void unpack2(unsigned long long v, float& lo, float& hi) {
    asm("mov.b64 {%0,%1}, %2;" : "=f"(lo), "=f"(hi) : "l"(v));
}
#define FMA2(d, a, b, c) \
    asm("fma.rn.f32x2 %0, %1, %2, %3;" : "=l"(d) : "l"(a), "l"(b), "l"(c))

// =============================================================================
// Kernel 1: per-batch brute-force exact KNN (top-20 smallest
//   d = sq_q + sq_m - 2*dot), one query per thread, candidates staged in smem.
//
// Fast path: sorted top-20 (val/idx) in registers, but sorted insertion runs
// only at geometric chunk boundaries. Within a chunk, survivors of the stale
// threshold tau (20th-smallest at last flush) are appended to a small local
// buffer (~4 instr divergent body). Expected appends ~10/lane/chunk, so the
// expensive 20-step insert chain runs warp-synchronously ~105x/lane instead
// of warp-divergently ~1830x/warp. Ascending-m processing keeps jax top_k
// tie ordering (earlier index wins on equal distance).
// =============================================================================
__device__ __forceinline__ void insert20(float v, int ii,
                                         float (&val)[K_NN], int (&idx)[K_NN]) {
#pragma unroll
    for (int j = 0; j < K_NN; j++) {
        bool lt = v < val[j];
        float vmax = lt ? val[j] : v;
        int   imax = lt ? idx[j] : ii;
        val[j] = lt ? v  : val[j];
        idx[j] = lt ? ii : idx[j];
        v = vmax; ii = imax;
    }
}

__global__ void knn_kernel(const float* __restrict__ x) {
    extern __shared__ float4 pts[];
    const int b = blockIdx.y;
    const float* xb = x + (size_t)b * N_PTS * 3;

    for (int i = threadIdx.x; i < N_PTS; i += blockDim.x) {
        float x0 = xb[i * 3 + 0], x1 = xb[i * 3 + 1], x2 = xb[i * 3 + 2];
        float sq = fmaf(x0, x0, fmaf(x1, x1, x2 * x2));
        pts[i] = make_float4(x0, x1, x2, sq);
    }
    __syncthreads();

    const int q = blockIdx.x * blockDim.x + threadIdx.x;
    const float4 qp = pts[q];

    float val[K_NN];
    int   idx[K_NN];
#pragma unroll
    for (int j = 0; j < K_NN; j++) { val[j] = 3.402823466e38f; idx[j] = 0; }

    // ---- init chunk: first 64 candidates, direct (divergent) insert ----
#pragma unroll 4
    for (int m = 0; m < 64; m++) {
        float4 p = pts[m];
        float t = fmaf(qp.x, p.x, fmaf(qp.y, p.y, qp.z * p.z));
        float d = (qp.w + p.w) - (t + t);
        if (d < val[K_NN - 1]) insert20(d, m, val, idx);
    }
    float tau = val[K_NN - 1];

    // ---- chunked scan with deferred buffer ----
    float bd[BUF_SZ];
    int   bm[BUF_SZ];
    int   cnt = 0;
    int   lo = 64;
    const short bnd[11] = {96, 144, 216, 324, 486, 729, 1093, 1640, 2460, 3690, 4096};

#pragma unroll 1
    for (int c = 0; c < 11; c++) {
        const int hi = bnd[c];
#pragma unroll 4
        for (int m = lo; m < hi; m++) {
            float4 p = pts[m];
            float t = fmaf(qp.x, p.x, fmaf(qp.y, p.y, qp.z * p.z));
            float d = (qp.w + p.w) - (t + t);
            if (d <= tau) {
                bd[cnt] = d; bm[cnt] = m; cnt++;
                if (cnt == BUF_SZ) {           // rare overflow safety
                    for (int i = 0; i < BUF_SZ; i++)
                        if (bd[i] < val[K_NN - 1]) insert20(bd[i], bm[i], val, idx);
                    cnt = 0; tau = val[K_NN - 1];
                }
            }
        }
        // boundary flush (warp-synchronous)
        for (int i = 0; i < cnt; i++)
            if (bd[i] < val[K_NN - 1]) insert20(bd[i], bm[i], val, idx);
        cnt = 0; tau = val[K_NN - 1];
        lo = hi;
    }

    int base = (b * N_PTS + q) * K_NN;
#pragma unroll
    for (int j = 0; j < K_NN; j++) g_idx[base + j] = idx[j];
}

// =============================================================================
// Kernel 2: fp64 moment accumulation for global BatchNorm statistics.
// h_c(edge) is affine in (xi, xj) -> mean/var need only 27 moments.
// Deterministic: block tree-reduce -> g_part, summed serially in finalize.
// =============================================================================
__global__ void stats_kernel(const float* __restrict__ x) {
    const int pt = blockIdx.x * blockDim.x + threadIdx.x;
    const int b = pt >> 12;
    const int gbase = b << 12;

    const float* xr = x + (size_t)pt * 3;
    double di0 = (double)xr[0], di1 = (double)xr[1], di2 = (double)xr[2];

    double sj0 = 0, sj1 = 0, sj2 = 0;
    double jj00 = 0, jj01 = 0, jj02 = 0, jj11 = 0, jj12 = 0, jj22 = 0;
    double ij00 = 0, ij01 = 0, ij02 = 0, ij10 = 0, ij11 = 0, ij12 = 0,
           ij20 = 0, ij21 = 0, ij22 = 0;

    const int* ip = g_idx + (size_t)pt * K_NN;
#pragma unroll 4
    for (int k = 0; k < K_NN; k++) {
        int j = __ldg(ip + k);
        const float* xp = x + (size_t)(gbase + j) * 3;
        double j0 = (double)__ldg(xp + 0);
        double j1 = (double)__ldg(xp + 1);
        double j2 = (double)__ldg(xp + 2);
        sj0 += j0; sj1 += j1; sj2 += j2;
        jj00 += j0 * j0; jj01 += j0 * j1; jj02 += j0 * j2;
        jj11 += j1 * j1; jj12 += j1 * j2; jj22 += j2 * j2;
        ij00 += di0 * j0; ij01 += di0 * j1; ij02 += di0 * j2;
        ij10 += di1 * j0; ij11 += di1 * j1; ij12 += di1 * j2;
        ij20 += di2 * j0; ij21 += di2 * j1; ij22 += di2 * j2;
    }

    double vals[NVALS] = {
        di0, di1, di2,
        di0 * di0, di0 * di1, di0 * di2, di1 * di1, di1 * di2, di2 * di2,
        sj0, sj1, sj2,
        jj00, jj01, jj02, jj11, jj12, jj22,
        ij00, ij01, ij02, ij10, ij11, ij12, ij20, ij21, ij22
    };

    __shared__ double red[256];
#pragma unroll 1
    for (int v = 0; v < NVALS; v++) {
        red[threadIdx.x] = vals[v];
        __syncthreads();
        for (int s = 128; s > 0; s >>= 1) {
            if (threadIdx.x < s) red[threadIdx.x] += red[threadIdx.x + s];
            __syncthreads();
        }
        if (threadIdx.x == 0) g_part[blockIdx.x * NVALS + v] = red[0];
        __syncthreads();
    }
}

// =============================================================================
// Kernel 3: finalize BN stats -> per-channel scale/shift (fp64 math).
// =============================================================================
__global__ void finalize_kernel(const float* __restrict__ w1,
                                const float* __restrict__ b1,
                                const float* __restrict__ gamma,
                                const float* __restrict__ beta) {
    __shared__ double S[NVALS];
    if (threadIdx.x < NVALS) {
        double s = 0.0;
        for (int bl = 0; bl < STAT_BLOCKS; bl++) s += g_part[bl * NVALS + threadIdx.x];
        S[threadIdx.x] = s;
    }
    __syncthreads();

    const int c = threadIdx.x;              // 64 threads
    const double M = (double)B_SZ * N_PTS * K_NN;
    const double Kd = (double)K_NN;

    double q0 = (double)w1[3 * CO + c], q1 = (double)w1[4 * CO + c], q2 = (double)w1[5 * CO + c];
    double p0 = (double)w1[0 * CO + c] - q0;
    double p1 = (double)w1[1 * CO + c] - q1;
    double p2 = (double)w1[2 * CO + c] - q2;
    double s_ = (double)b1[c];

    double Si0 = Kd * S[0], Si1 = Kd * S[1], Si2 = Kd * S[2];
    double i00 = Kd * S[3], i01 = Kd * S[4], i02 = Kd * S[5];
    double i11 = Kd * S[6], i12 = Kd * S[7], i22 = Kd * S[8];
    double Sj0 = S[9], Sj1 = S[10], Sj2 = S[11];
    double j00 = S[12], j01 = S[13], j02 = S[14], j11 = S[15], j12 = S[16], j22 = S[17];

    double pSi = p0 * Si0 + p1 * Si1 + p2 * Si2;
    double qSj = q0 * Sj0 + q1 * Sj1 + q2 * Sj2;
    double mean = (pSi + qSj) / M + s_;

    double pMp = p0 * p0 * i00 + p1 * p1 * i11 + p2 * p2 * i22 +
                 2.0 * (p0 * p1 * i01 + p0 * p2 * i02 + p1 * p2 * i12);
    double qMq = q0 * q0 * j00 + q1 * q1 * j11 + q2 * q2 * j22 +
                 2.0 * (q0 * q1 * j01 + q0 * q2 * j02 + q1 * q2 * j12);
    double pMq = p0 * (q0 * S[18] + q1 * S[19] + q2 * S[20]) +
                 p1 * (q0 * S[21] + q1 * S[22] + q2 * S[23]) +
                 p2 * (q0 * S[24] + q1 * S[25] + q2 * S[26]);

    double sumsq = pMp + qMq + 2.0 * pMq + 2.0 * s_ * (pSi + qSj) + M * s_ * s_;
    double var = sumsq / M - mean * mean;
    double rstd = 1.0 / sqrt(var + 1e-5);

    double g = (double)gamma[c];
    g_scale[c] = (float)(g * rstd);
    g_shift[c] = (float)((double)beta[c] - mean * g * rstd);
}

// =============================================================================
// Kernel 4: fused edge-MLP + BN + ReLU + (r @ w2) + max over K.
// One warp per point: 2 output channels per lane. Stage-2 GEMM uses packed
// fma.rn.f32x2 (FFMA2): 20 k-accumulators -> 10 packed u64 accumulators,
// halving fma-pipe ops. BN scale/shift folded into w1/b1 (saves 2 fma/k).
// =============================================================================
__global__ void __launch_bounds__(256, 3)
main_kernel(const float* __restrict__ x,
            const float* __restrict__ w1,
            const float* __restrict__ b1,
            const float* __restrict__ w2,
            const float* __restrict__ b2,
            float* __restrict__ out) {
    extern __shared__ float sm[];
    float* w2s = sm;               // 64*64
    float* rt  = sm + CO * CO;     // 8 warps * 64 * 20

    for (int i = threadIdx.x; i < CO * CO; i += blockDim.x) w2s[i] = w2[i];
    __syncthreads();

    const int w = threadIdx.x >> 5;
    const int l = threadIdx.x & 31;
    const int pt = blockIdx.x * 8 + w;
    float* rw = rt + w * (CO * K_NN);

    const int ca = l, cb = l + 32;

    const float sca = g_scale[ca], scb = g_scale[cb];
    float w1a[6], w1b[6];
#pragma unroll
    for (int r = 0; r < 6; r++) {
        w1a[r] = __ldg(w1 + r * CO + ca) * sca;
        w1b[r] = __ldg(w1 + r * CO + cb) * scb;
    }
    const float b1a = fmaf(__ldg(b1 + ca), sca, g_shift[ca]);
    const float b1b = fmaf(__ldg(b1 + cb), scb, g_shift[cb]);

    const int b = pt >> 12;
    const int gbase = b << 12;
    const float* xr = x + (size_t)pt * 3;
    const float xi0 = __ldg(xr), xi1 = __ldg(xr + 1), xi2 = __ldg(xr + 2);
    const int* ip = g_idx + (size_t)pt * K_NN;

    // ---- stage 1: r[c][k] = relu(scale*(e@w1) + shift), BN folded ----
#pragma unroll 4
    for (int k = 0; k < K_NN; k++) {
        int j = __ldg(ip + k);
        const float* xp = x + (size_t)(gbase + j) * 3;
        float d0 = __ldg(xp)     - xi0;
        float d1 = __ldg(xp + 1) - xi1;
        float d2 = __ldg(xp + 2) - xi2;

        float ha = b1a;
        ha = fmaf(xi0, w1a[0], ha); ha = fmaf(xi1, w1a[1], ha); ha = fmaf(xi2, w1a[2], ha);
        ha = fmaf(d0,  w1a[3], ha); ha = fmaf(d1,  w1a[4], ha); ha = fmaf(d2,  w1a[5], ha);
        float hb = b1b;
        hb = fmaf(xi0, w1b[0], hb); hb = fmaf(xi1, w1b[1], hb); hb = fmaf(xi2, w1b[2], hb);
        hb = fmaf(d0,  w1b[3], hb); hb = fmaf(d1,  w1b[4], hb); hb = fmaf(d2,  w1b[5], hb);

        rw[ca * K_NN + k] = fmaxf(ha, 0.0f);
        rw[cb * K_NN + k] = fmaxf(hb, 0.0f);
    }
    __syncwarp();

    // ---- stage 2: packed FFMA2 GEMM, acc[i] holds k=(2i, 2i+1) ----
    unsigned long long acca[K_NN / 2], accb[K_NN / 2];
#pragma unroll
    for (int i = 0; i < K_NN / 2; i++) { acca[i] = 0ULL; accb[i] = 0ULL; }

#pragma unroll 4
    for (int c = 0; c < CO; c++) {
        float wa = w2s[c * CO + ca];
        float wb = w2s[c * CO + cb];
        unsigned long long wa2 = pack2(wa, wa);
        unsigned long long wb2 = pack2(wb, wb);
        const ulonglong2* r2 = (const ulonglong2*)(rw + c * K_NN);
#pragma unroll
        for (int t = 0; t < 5; t++) {
            ulonglong2 rv = r2[t];
            FMA2(acca[2 * t],     rv.x, wa2, acca[2 * t]);
            FMA2(acca[2 * t + 1], rv.y, wa2, acca[2 * t + 1]);
            FMA2(accb[2 * t],     rv.x, wb2, accb[2 * t]);
            FMA2(accb[2 * t + 1], rv.y, wb2, accb[2 * t + 1]);
        }
    }

    float ma = -3.402823466e38f, mb = -3.402823466e38f;
#pragma unroll
    for (int i = 0; i < K_NN / 2; i++) {
        float a0, a1, b0, b1v;
        unpack2(acca[i], a0, a1);
        unpack2(accb[i], b0, b1v);
        ma = fmaxf(ma, fmaxf(a0, a1));
        mb = fmaxf(mb, fmaxf(b0, b1v));
    }

    out[(size_t)pt * CO + ca] = ma + __ldg(b2 + ca);
    out[(size_t)pt * CO + cb] = mb + __ldg(b2 + cb);
}

// =============================================================================
extern "C" void kernel_launch(void* const* d_in, const int* in_sizes, int n_in,
                              void* d_out, int out_size) {
    const float* x     = (const float*)d_in[0];
    // d_in[1] = batch indices (implied by layout; unused)
    const float* w1    = (const float*)d_in[2];
    const float* b1    = (const float*)d_in[3];
    const float* gamma = (const float*)d_in[4];
    const float* beta  = (const float*)d_in[5];
    const float* w2    = (const float*)d_in[6];
    const float* b2    = (const float*)d_in[7];
    float* out = (float*)d_out;

    const int knn_smem  = N_PTS * sizeof(float4);                       // 64 KB
    const int main_smem = (CO * CO + 8 * CO * K_NN) * sizeof(float);    // 56 KB

    cudaFuncSetAttribute(knn_kernel,  cudaFuncAttributeMaxDynamicSharedMemorySize, knn_smem);
    cudaFuncSetAttribute(main_kernel, cudaFuncAttributeMaxDynamicSharedMemorySize, main_smem);

    knn_kernel<<<dim3(N_PTS / 256, B_SZ), 256, knn_smem>>>(x);
    stats_kernel<<<STAT_BLOCKS, 256>>>(x);
    finalize_kernel<<<1, 64>>>(w1, b1, gamma, beta);
    main_kernel<<<(B_SZ * N_PTS) / 8, 256, main_smem>>>(x, w1, b1, w2, b2, out);
}

// round 3
// speedup vs baseline: 1.6511x; 1.1405x over previous
#include <cuda_runtime.h>

#define B_SZ 16
#define N_PTS 4096
#define K_NN 20
#define CO 64
#define STAT_BLOCKS 256
#define NVALS 27
#define PEND 6
#define NCHUNK 30

// ---------------- scratch (static device allocations, allowed) ----------------
__device__ int    g_idx[B_SZ * N_PTS * K_NN];       // 5.24 MB
__device__ double g_part[STAT_BLOCKS * NVALS];
__device__ float  g_scale[CO];
__device__ float  g_shift[CO];

// packed f32x2 helpers (sm_100+ PTX)
__device__ __forceinline__ unsigned long long pack2(float lo, float hi) {
    unsigned long long r;
    asm("mov.b64 %0, {%1,%2};" : "=l"(r) : "f"(lo), "f"(hi));
    return r;
}
__device__ __forceinline__ void unpack2(unsigned long long v, float& lo, float& hi) {
    asm("mov.b64 {%0,%1}, %2;" : "=f"(lo), "=f"(hi) : "l"(v));
}
#define FMA2(d, a, b, c) \
    asm("fma.rn.f32x2 %0, %1, %2, %3;" : "=l"(d) : "l"(a), "l"(b), "l"(c))

// =============================================================================
// Kernel 1: per-batch brute-force exact KNN, top-20 smallest
//   d = (sq_q + sq_m) - 2*dot   (exact __fmul/__fadd form, matches reference)
//
// Sorted top-20 (val,idx) in registers. Triggered candidates are appended into
// PEND fixed *register* slots (compile-time-unrolled select, never local mem)
// and bubble-inserted warp-uniformly at geometric chunk boundaries. Overflow
// (pend full) falls back to an immediate insert (rare). Ties keep earlier
// index (strict <, ascending-m processing) to match jax top_k.
// =============================================================================
__device__ __forceinline__ void insert20(float v, int ii,
                                         float (&val)[K_NN], int (&idx)[K_NN]) {
#pragma unroll
    for (int j = 0; j < K_NN; j++) {
        bool lt = v < val[j];
        float nv = lt ? v  : val[j];
        int   ni = lt ? ii : idx[j];
        float cv = lt ? val[j] : v;
        int   ci = lt ? idx[j] : ii;
        val[j] = nv; idx[j] = ni;
        v = cv; ii = ci;
    }
}

__global__ void knn_kernel(const float* __restrict__ x) {
    extern __shared__ float4 pts[];
    const int b = blockIdx.y;
    const float* xb = x + (size_t)b * N_PTS * 3;

    for (int i = threadIdx.x; i < N_PTS; i += blockDim.x) {
        float x0 = xb[i * 3 + 0], x1 = xb[i * 3 + 1], x2 = xb[i * 3 + 2];
        float sq = __fadd_rn(__fadd_rn(__fmul_rn(x0, x0), __fmul_rn(x1, x1)),
                             __fmul_rn(x2, x2));
        pts[i] = make_float4(x0, x1, x2, sq);
    }
    __syncthreads();

    const int q = blockIdx.x * blockDim.x + threadIdx.x;
    const float4 qp = pts[q];

    float val[K_NN];
    int   idx[K_NN];
#pragma unroll
    for (int j = 0; j < K_NN; j++) { val[j] = 3.402823466e38f; idx[j] = 0; }

    // ---- direct phase: first 64 candidates, immediate insert ----
#pragma unroll 2
    for (int m = 0; m < 64; m++) {
        float4 p = pts[m];
        float t = __fadd_rn(__fadd_rn(__fmul_rn(qp.x, p.x), __fmul_rn(qp.y, p.y)),
                            __fmul_rn(qp.z, p.z));
        float d = __fsub_rn(__fadd_rn(qp.w, p.w), __fmul_rn(2.0f, t));
        if (d < val[K_NN - 1]) insert20(d, m, val, idx);
    }
    float v19 = val[K_NN - 1];

    // ---- chunked scan with register pending slots ----
    float pv[PEND];
    int   pi[PEND];
#pragma unroll
    for (int s = 0; s < PEND; s++) { pv[s] = 3.402823466e38f; pi[s] = 0; }
    int pend = 0;

    static const short bnd[NCHUNK] = {
        74, 85, 98, 112, 129, 148, 170, 196, 225, 259,
        298, 343, 394, 453, 521, 599, 689, 793, 912, 1049,
        1206, 1387, 1595, 1834, 2109, 2425, 2789, 3207, 3688, 4096};

    int lo = 64;
#pragma unroll 1
    for (int c = 0; c < NCHUNK; c++) {
        const int hi = bnd[c];
#pragma unroll 2
        for (int m = lo; m < hi; m++) {
            float4 p = pts[m];
            float t = __fadd_rn(__fadd_rn(__fmul_rn(qp.x, p.x), __fmul_rn(qp.y, p.y)),
                                __fmul_rn(qp.z, p.z));
            float d = __fsub_rn(__fadd_rn(qp.w, p.w), __fmul_rn(2.0f, t));
            if (d < v19) {
                if (pend < PEND) {
#pragma unroll
                    for (int s = 0; s < PEND; s++) {
                        bool w = (pend == s);
                        pv[s] = w ? d : pv[s];
                        pi[s] = w ? m : pi[s];
                    }
                    pend++;
                } else {
                    insert20(d, m, val, idx);   // rare overflow path
                }
            }
        }
        // warp-uniform flush (+INF slots are no-ops)
#pragma unroll
        for (int s = 0; s < PEND; s++) {
            insert20(pv[s], pi[s], val, idx);
            pv[s] = 3.402823466e38f;
        }
        pend = 0;
        v19 = val[K_NN - 1];
        lo = hi;
    }

    int base = (b * N_PTS + q) * K_NN;
#pragma unroll
    for (int j = 0; j < K_NN; j++) g_idx[base + j] = idx[j];
}

// =============================================================================
// Kernel 2: fp64 moment accumulation for global BatchNorm statistics.
// h_c(edge) is affine in (xi, xj) -> mean/var need only 27 moments.
// Deterministic: warp shuffle-reduce -> smem -> per-block partial, summed
// serially in finalize.
// =============================================================================
__global__ void stats_kernel(const float* __restrict__ x) {
    const int pt = blockIdx.x * blockDim.x + threadIdx.x;
    const int b = pt >> 12;
    const int gbase = b << 12;

    const float* xr = x + (size_t)pt * 3;
    double di0 = (double)xr[0], di1 = (double)xr[1], di2 = (double)xr[2];

    double sj0 = 0, sj1 = 0, sj2 = 0;
    double jj00 = 0, jj01 = 0, jj02 = 0, jj11 = 0, jj12 = 0, jj22 = 0;
    double ij00 = 0, ij01 = 0, ij02 = 0, ij10 = 0, ij11 = 0, ij12 = 0,
           ij20 = 0, ij21 = 0, ij22 = 0;

    const int* ip = g_idx + (size_t)pt * K_NN;
#pragma unroll 4
    for (int k = 0; k < K_NN; k++) {
        int j = __ldg(ip + k);
        const float* xp = x + (size_t)(gbase + j) * 3;
        double j0 = (double)__ldg(xp + 0);
        double j1 = (double)__ldg(xp + 1);
        double j2 = (double)__ldg(xp + 2);
        sj0 += j0; sj1 += j1; sj2 += j2;
        jj00 += j0 * j0; jj01 += j0 * j1; jj02 += j0 * j2;
        jj11 += j1 * j1; jj12 += j1 * j2; jj22 += j2 * j2;
        ij00 += di0 * j0; ij01 += di0 * j1; ij02 += di0 * j2;
        ij10 += di1 * j0; ij11 += di1 * j1; ij12 += di1 * j2;
        ij20 += di2 * j0; ij21 += di2 * j1; ij22 += di2 * j2;
    }

    double vals[NVALS] = {
        di0, di1, di2,
        di0 * di0, di0 * di1, di0 * di2, di1 * di1, di1 * di2, di2 * di2,
        sj0, sj1, sj2,
        jj00, jj01, jj02, jj11, jj12, jj22,
        ij00, ij01, ij02, ij10, ij11, ij12, ij20, ij21, ij22
    };

    __shared__ double wsum[8][NVALS];
    const int wid = threadIdx.x >> 5;
    const int lid = threadIdx.x & 31;

#pragma unroll
    for (int v = 0; v < NVALS; v++) {
        double s = vals[v];
#pragma unroll
        for (int o = 16; o > 0; o >>= 1) s += __shfl_xor_sync(0xFFFFFFFFu, s, o);
        if (lid == 0) wsum[wid][v] = s;
    }
    __syncthreads();

    if (threadIdx.x < NVALS) {
        double s = 0.0;
#pragma unroll
        for (int w = 0; w < 8; w++) s += wsum[w][threadIdx.x];
        g_part[blockIdx.x * NVALS + threadIdx.x] = s;
    }
}

// =============================================================================
// Kernel 3: finalize BN stats -> per-channel scale/shift (fp64 math).
// =============================================================================
__global__ void finalize_kernel(const float* __restrict__ w1,
                                const float* __restrict__ b1,
                                const float* __restrict__ gamma,
                                const float* __restrict__ beta) {
    __shared__ double S[NVALS];
    if (threadIdx.x < NVALS) {
        double s = 0.0;
        for (int bl = 0; bl < STAT_BLOCKS; bl++) s += g_part[bl * NVALS + threadIdx.x];
        S[threadIdx.x] = s;
    }
    __syncthreads();

    const int c = threadIdx.x;              // 64 threads
    const double M = (double)B_SZ * N_PTS * K_NN;
    const double Kd = (double)K_NN;

    double q0 = (double)w1[3 * CO + c], q1 = (double)w1[4 * CO + c], q2 = (double)w1[5 * CO + c];
    double p0 = (double)w1[0 * CO + c] - q0;
    double p1 = (double)w1[1 * CO + c] - q1;
    double p2 = (double)w1[2 * CO + c] - q2;
    double s_ = (double)b1[c];

    double Si0 = Kd * S[0], Si1 = Kd * S[1], Si2 = Kd * S[2];
    double i00 = Kd * S[3], i01 = Kd * S[4], i02 = Kd * S[5];
    double i11 = Kd * S[6], i12 = Kd * S[7], i22 = Kd * S[8];
    double Sj0 = S[9], Sj1 = S[10], Sj2 = S[11];
    double j00 = S[12], j01 = S[13], j02 = S[14], j11 = S[15], j12 = S[16], j22 = S[17];

    double pSi = p0 * Si0 + p1 * Si1 + p2 * Si2;
    double qSj = q0 * Sj0 + q1 * Sj1 + q2 * Sj2;
    double mean = (pSi + qSj) / M + s_;

    double pMp = p0 * p0 * i00 + p1 * p1 * i11 + p2 * p2 * i22 +
                 2.0 * (p0 * p1 * i01 + p0 * p2 * i02 + p1 * p2 * i12);
    double qMq = q0 * q0 * j00 + q1 * q1 * j11 + q2 * q2 * j22 +
                 2.0 * (q0 * q1 * j01 + q0 * q2 * j02 + q1 * q2 * j12);
    double pMq = p0 * (q0 * S[18] + q1 * S[19] + q2 * S[20]) +
                 p1 * (q0 * S[21] + q1 * S[22] + q2 * S[23]) +
                 p2 * (q0 * S[24] + q1 * S[25] + q2 * S[26]);

    double sumsq = pMp + qMq + 2.0 * pMq + 2.0 * s_ * (pSi + qSj) + M * s_ * s_;
    double var = sumsq / M - mean * mean;
    double rstd = 1.0 / sqrt(var + 1e-5);

    double g = (double)gamma[c];
    g_scale[c] = (float)(g * rstd);
    g_shift[c] = (float)((double)beta[c] - mean * g * rstd);
}

// =============================================================================
// Kernel 4: fused edge-MLP + BN + ReLU + (r @ w2) + max over K.
// One warp per point: 2 output channels per lane. Stage-2 GEMM uses packed
// fma.rn.f32x2 (FFMA2). BN scale/shift folded into w1/b1.
// =============================================================================
__global__ void __launch_bounds__(256, 3)
main_kernel(const float* __restrict__ x,
            const float* __restrict__ w1,
            const float* __restrict__ b1,
            const float* __restrict__ w2,
            const float* __restrict__ b2,
            float* __restrict__ out) {
    extern __shared__ float sm[];
    float* w2s = sm;               // 64*64
    float* rt  = sm + CO * CO;     // 8 warps * 64 * 20

    for (int i = threadIdx.x; i < CO * CO; i += blockDim.x) w2s[i] = w2[i];
    __syncthreads();

    const int w = threadIdx.x >> 5;
    const int l = threadIdx.x & 31;
    const int pt = blockIdx.x * 8 + w;
    float* rw = rt + w * (CO * K_NN);

    const int ca = l, cb = l + 32;

    const float sca = g_scale[ca], scb = g_scale[cb];
    float w1a[6], w1b[6];
#pragma unroll
    for (int r = 0; r < 6; r++) {
        w1a[r] = __ldg(w1 + r * CO + ca) * sca;
        w1b[r] = __ldg(w1 + r * CO + cb) * scb;
    }
    const float b1a = fmaf(__ldg(b1 + ca), sca, g_shift[ca]);
    const float b1b = fmaf(__ldg(b1 + cb), scb, g_shift[cb]);

    const int b = pt >> 12;
    const int gbase = b << 12;
    const float* xr = x + (size_t)pt * 3;
    const float xi0 = __ldg(xr), xi1 = __ldg(xr + 1), xi2 = __ldg(xr + 2);
    const int* ip = g_idx + (size_t)pt * K_NN;

    // ---- stage 1: r[c][k] = relu(scale*(e@w1) + shift), BN folded ----
#pragma unroll 4
    for (int k = 0; k < K_NN; k++) {
        int j = __ldg(ip + k);
        const float* xp = x + (size_t)(gbase + j) * 3;
        float d0 = __ldg(xp)     - xi0;
        float d1 = __ldg(xp + 1) - xi1;
        float d2 = __ldg(xp + 2) - xi2;

        float ha = b1a;
        ha = fmaf(xi0, w1a[0], ha); ha = fmaf(xi1, w1a[1], ha); ha = fmaf(xi2, w1a[2], ha);
        ha = fmaf(d0,  w1a[3], ha); ha = fmaf(d1,  w1a[4], ha); ha = fmaf(d2,  w1a[5], ha);
        float hb = b1b;
        hb = fmaf(xi0, w1b[0], hb); hb = fmaf(xi1, w1b[1], hb); hb = fmaf(xi2, w1b[2], hb);
        hb = fmaf(d0,  w1b[3], hb); hb = fmaf(d1,  w1b[4], hb); hb = fmaf(d2,  w1b[5], hb);

        rw[ca * K_NN + k] = fmaxf(ha, 0.0f);
        rw[cb * K_NN + k] = fmaxf(hb, 0.0f);
    }
    __syncwarp();

    // ---- stage 2: packed FFMA2 GEMM, acc[i] holds k=(2i, 2i+1) ----
    unsigned long long acca[K_NN / 2], accb[K_NN / 2];
#pragma unroll
    for (int i = 0; i < K_NN / 2; i++) { acca[i] = 0ULL; accb[i] = 0ULL; }

#pragma unroll 4
    for (int c = 0; c < CO; c++) {
        float wa = w2s[c * CO + ca];
        float wb = w2s[c * CO + cb];
        unsigned long long wa2 = pack2(wa, wa);
        unsigned long long wb2 = pack2(wb, wb);
        const ulonglong2* r2 = (const ulonglong2*)(rw + c * K_NN);
#pragma unroll
        for (int t = 0; t < 5; t++) {
            ulonglong2 rv = r2[t];
            FMA2(acca[2 * t],     rv.x, wa2, acca[2 * t]);
            FMA2(acca[2 * t + 1], rv.y, wa2, acca[2 * t + 1]);
            FMA2(accb[2 * t],     rv.x, wb2, accb[2 * t]);
            FMA2(accb[2 * t + 1], rv.y, wb2, accb[2 * t + 1]);
        }
    }

    float ma = -3.402823466e38f, mb = -3.402823466e38f;
#pragma unroll
    for (int i = 0; i < K_NN / 2; i++) {
        float a0, a1, b0, b1v;
        unpack2(acca[i], a0, a1);
        unpack2(accb[i], b0, b1v);
        ma = fmaxf(ma, fmaxf(a0, a1));
        mb = fmaxf(mb, fmaxf(b0, b1v));
    }

    out[(size_t)pt * CO + ca] = ma + __ldg(b2 + ca);
    out[(size_t)pt * CO + cb] = mb + __ldg(b2 + cb);
}

// =============================================================================
extern "C" void kernel_launch(void* const* d_in, const int* in_sizes, int n_in,
                              void* d_out, int out_size) {
    const float* x     = (const float*)d_in[0];
    // d_in[1] = batch indices (implied by layout; unused)
    const float* w1    = (const float*)d_in[2];
    const float* b1    = (const float*)d_in[3];
    const float* gamma = (const float*)d_in[4];
    const float* beta  = (const float*)d_in[5];
    const float* w2    = (const float*)d_in[6];
    const float* b2    = (const float*)d_in[7];
    float* out = (float*)d_out;

    const int knn_smem  = N_PTS * sizeof(float4);                       // 64 KB
    const int main_smem = (CO * CO + 8 * CO * K_NN) * sizeof(float);    // 56 KB

    cudaFuncSetAttribute(knn_kernel,  cudaFuncAttributeMaxDynamicSharedMemorySize, knn_smem);
    cudaFuncSetAttribute(main_kernel, cudaFuncAttributeMaxDynamicSharedMemorySize, main_smem);

    knn_kernel<<<dim3(N_PTS / 256, B_SZ), 256, knn_smem>>>(x);
    stats_kernel<<<STAT_BLOCKS, 256>>>(x);
    finalize_kernel<<<1, 64>>>(w1, b1, gamma, beta);
    main_kernel<<<(B_SZ * N_PTS) / 8, 256, main_smem>>>(x, w1, b1, w2, b2, out);
}

// round 4
// speedup vs baseline: 1.9521x; 1.1823x over previous
#include <cuda_runtime.h>

#define B_SZ 16
#define N_PTS 4096
#define K_NN 20
#define CO 64
#define STAT_BLOCKS 256
#define NVALS 27
#define CAP 24          // per-lane smem stack capacity (slots)
#define NCHUNK_B 16

// ---------------- scratch (static device allocations, allowed) ----------------
__device__ int    g_idx[B_SZ * N_PTS * K_NN];       // 5.24 MB
__device__ double g_part[STAT_BLOCKS * NVALS];
__device__ float  g_scale[CO];
__device__ float  g_shift[CO];

// packed f32x2 helpers (sm_100+ PTX)
__device__ __forceinline__ unsigned long long pack2(float lo, float hi) {
    unsigned long long r;
    asm("mov.b64 %0, {%1,%2};" : "=l"(r) : "f"(lo), "f"(hi));
    return r;
}
__device__ __forceinline__ void unpack2(unsigned long long v, float& lo, float& hi) {
    asm("mov.b64 {%0,%1}, %2;" : "=f"(lo), "=f"(hi) : "l"(v));
}
#define FMA2(d, a, b, c) \
    asm("fma.rn.f32x2 %0, %1, %2, %3;" : "=l"(d) : "l"(a), "l"(b), "l"(c))

// =============================================================================
// Kernel 1: per-batch brute-force exact KNN, top-20 smallest distances.
//
// Hot loop is 100% branch-free: survivors of the (stale) 20th-smallest
// threshold are appended via predicated st.shared (inline PTX, no BSSY) to a
// per-lane conflict-free smem stack (slot stride 256B = 32 lanes x 8B).
// At 16 geometric chunk boundaries the stack is replayed into the sorted
// top-20 registers and the threshold refreshed. Stack overflow (P ~ 1e-6)
// falls back to a deterministic rescan of that chunk. Ascending-m order +
// strict < keeps jax top_k tie semantics (earlier index wins).
// =============================================================================
__device__ __forceinline__ void insert20(float v, int ii,
                                         float (&val)[K_NN], int (&idx)[K_NN]) {
#pragma unroll
    for (int j = 0; j < K_NN; j++) {
        bool lt = v < val[j];
        float nv = lt ? v  : val[j];
        int   ni = lt ? ii : idx[j];
        float cv = lt ? val[j] : v;
        int   ci = lt ? idx[j] : ii;
        val[j] = nv; idx[j] = ni;
        v = cv; ii = ci;
    }
}

__global__ void __launch_bounds__(512, 1)
knn_kernel(const float* __restrict__ x) {
    extern __shared__ char smem_raw[];
    float4* pts = (float4*)smem_raw;                       // 4096*16 = 64 KB
    char*   stacks = smem_raw + N_PTS * sizeof(float4);    // 16 warps * 24*256 = 96 KB

    const int b    = blockIdx.x >> 3;          // 8 blocks per batch
    const int qblk = blockIdx.x & 7;
    const float* xb = x + (size_t)b * N_PTS * 3;

    for (int i = threadIdx.x; i < N_PTS; i += 512) {
        float x0 = xb[i * 3 + 0], x1 = xb[i * 3 + 1], x2 = xb[i * 3 + 2];
        float sq = fmaf(x0, x0, fmaf(x1, x1, x2 * x2));
        pts[i] = make_float4(x0, x1, x2, sq);
    }
    __syncthreads();

    const int q = qblk * 512 + threadIdx.x;
    const float4 qp = pts[q];
    const float m2x = -2.0f * qp.x, m2y = -2.0f * qp.y, m2z = -2.0f * qp.z;
    const float qw = qp.w;

    // per-lane stack addressing (shared address space)
    const unsigned sbase =
        (unsigned)__cvta_generic_to_shared(
            stacks + (size_t)(threadIdx.x >> 5) * (CAP * 256)) +
        (threadIdx.x & 31) * 8;
    const unsigned limit = sbase + CAP * 256;
    unsigned addr = sbase;

    float val[K_NN];
    int   idx[K_NN];
#pragma unroll
    for (int j = 0; j < K_NN; j++) { val[j] = 3.402823466e38f; idx[j] = 0; }

    // ---- init: first 20 candidates, unconditional insert ----
#pragma unroll
    for (int m = 0; m < K_NN; m++) {
        float4 p = pts[m];
        float d = fmaf(m2x, p.x, fmaf(m2y, p.y, fmaf(m2z, p.z, p.w))) + qw;
        insert20(d, m, val, idx);
    }
    float v19 = val[K_NN - 1];

    static const short bnd[NCHUNK_B] = {
        28, 39, 55, 77, 108, 151, 211, 296,
        414, 580, 812, 1137, 1592, 2229, 3120, 4096};

    int lo = K_NN;
#pragma unroll 1
    for (int c = 0; c < NCHUNK_B; c++) {
        const int hi = bnd[c];
        // ---- branch-free scan ----
#pragma unroll 4
        for (int m = lo; m < hi; m++) {
            float4 p = pts[m];
            float d = fmaf(m2x, p.x, fmaf(m2y, p.y, fmaf(m2z, p.z, p.w))) + qw;
            asm volatile(
                "{\n\t"
                ".reg .pred p;\n\t"
                "setp.lt.f32 p, %1, %2;\n\t"
                "setp.lt.and.u32 p, %0, %3, p;\n\t"
                "@p st.shared.v2.b32 [%0], {%4, %5};\n\t"
                "@p add.u32 %0, %0, 256;\n\t"
                "}"
                : "+r"(addr)
                : "f"(d), "f"(v19), "r"(limit), "r"(__float_as_int(d)), "r"(m));
        }
        // ---- flush: replay stack into sorted top-20 ----
        const bool ovf = (addr >= limit);
        const unsigned stop = ovf ? sbase : addr;
        for (unsigned pp = sbase; pp < stop; pp += 256) {
            unsigned e0, e1;
            asm volatile("ld.shared.v2.b32 {%0,%1}, [%2];"
                         : "=r"(e0), "=r"(e1) : "r"(pp));
            float dv = __int_as_float(e0);
            if (dv < val[K_NN - 1]) insert20(dv, (int)e1, val, idx);
        }
        if (__any_sync(0xFFFFFFFFu, ovf)) {      // rare deterministic fallback
            for (int m = lo; m < hi; m++) {
                float4 p = pts[m];
                float d = fmaf(m2x, p.x, fmaf(m2y, p.y, fmaf(m2z, p.z, p.w))) + qw;
                if (ovf && d < val[K_NN - 1]) insert20(d, m, val, idx);
            }
        }
        addr = sbase;
        v19 = val[K_NN - 1];
        lo = hi;
    }

    int base = (b * N_PTS + q) * K_NN;
#pragma unroll
    for (int j = 0; j < K_NN; j++) g_idx[base + j] = idx[j];
}

// =============================================================================
// Kernel 2: fp64 moment accumulation for global BatchNorm statistics.
// h_c(edge) is affine in (xi, xj) -> mean/var need only 27 moments.
// Deterministic: warp shuffle-reduce -> smem -> per-block partial, summed
// serially in finalize.
// =============================================================================
__global__ void stats_kernel(const float* __restrict__ x) {
    const int pt = blockIdx.x * blockDim.x + threadIdx.x;
    const int b = pt >> 12;
    const int gbase = b << 12;

    const float* xr = x + (size_t)pt * 3;
    double di0 = (double)xr[0], di1 = (double)xr[1], di2 = (double)xr[2];

    double sj0 = 0, sj1 = 0, sj2 = 0;
    double jj00 = 0, jj01 = 0, jj02 = 0, jj11 = 0, jj12 = 0, jj22 = 0;
    double ij00 = 0, ij01 = 0, ij02 = 0, ij10 = 0, ij11 = 0, ij12 = 0,
           ij20 = 0, ij21 = 0, ij22 = 0;

    const int* ip = g_idx + (size_t)pt * K_NN;
#pragma unroll 4
    for (int k = 0; k < K_NN; k++) {
        int j = __ldg(ip + k);
        const float* xp = x + (size_t)(gbase + j) * 3;
        double j0 = (double)__ldg(xp + 0);
        double j1 = (double)__ldg(xp + 1);
        double j2 = (double)__ldg(xp + 2);
        sj0 += j0; sj1 += j1; sj2 += j2;
        jj00 += j0 * j0; jj01 += j0 * j1; jj02 += j0 * j2;
        jj11 += j1 * j1; jj12 += j1 * j2; jj22 += j2 * j2;
        ij00 += di0 * j0; ij01 += di0 * j1; ij02 += di0 * j2;
        ij10 += di1 * j0; ij11 += di1 * j1; ij12 += di1 * j2;
        ij20 += di2 * j0; ij21 += di2 * j1; ij22 += di2 * j2;
    }

    double vals[NVALS] = {
        di0, di1, di2,
        di0 * di0, di0 * di1, di0 * di2, di1 * di1, di1 * di2, di2 * di2,
        sj0, sj1, sj2,
        jj00, jj01, jj02, jj11, jj12, jj22,
        ij00, ij01, ij02, ij10, ij11, ij12, ij20, ij21, ij22
    };

    __shared__ double wsum[8][NVALS];
    const int wid = threadIdx.x >> 5;
    const int lid = threadIdx.x & 31;

#pragma unroll
    for (int v = 0; v < NVALS; v++) {
        double s = vals[v];
#pragma unroll
        for (int o = 16; o > 0; o >>= 1) s += __shfl_xor_sync(0xFFFFFFFFu, s, o);
        if (lid == 0) wsum[wid][v] = s;
    }
    __syncthreads();

    if (threadIdx.x < NVALS) {
        double s = 0.0;
#pragma unroll
        for (int w = 0; w < 8; w++) s += wsum[w][threadIdx.x];
        g_part[blockIdx.x * NVALS + threadIdx.x] = s;
    }
}

// =============================================================================
// Kernel 3: finalize BN stats -> per-channel scale/shift (fp64 math).
// =============================================================================
__global__ void finalize_kernel(const float* __restrict__ w1,
                                const float* __restrict__ b1,
                                const float* __restrict__ gamma,
                                const float* __restrict__ beta) {
    __shared__ double S[NVALS];
    if (threadIdx.x < NVALS) {
        double s = 0.0;
        for (int bl = 0; bl < STAT_BLOCKS; bl++) s += g_part[bl * NVALS + threadIdx.x];
        S[threadIdx.x] = s;
    }
    __syncthreads();

    const int c = threadIdx.x;              // 64 threads
    const double M = (double)B_SZ * N_PTS * K_NN;
    const double Kd = (double)K_NN;

    double q0 = (double)w1[3 * CO + c], q1 = (double)w1[4 * CO + c], q2 = (double)w1[5 * CO + c];
    double p0 = (double)w1[0 * CO + c] - q0;
    double p1 = (double)w1[1 * CO + c] - q1;
    double p2 = (double)w1[2 * CO + c] - q2;
    double s_ = (double)b1[c];

    double Si0 = Kd * S[0], Si1 = Kd * S[1], Si2 = Kd * S[2];
    double i00 = Kd * S[3], i01 = Kd * S[4], i02 = Kd * S[5];
    double i11 = Kd * S[6], i12 = Kd * S[7], i22 = Kd * S[8];
    double Sj0 = S[9], Sj1 = S[10], Sj2 = S[11];
    double j00 = S[12], j01 = S[13], j02 = S[14], j11 = S[15], j12 = S[16], j22 = S[17];

    double pSi = p0 * Si0 + p1 * Si1 + p2 * Si2;
    double qSj = q0 * Sj0 + q1 * Sj1 + q2 * Sj2;
    double mean = (pSi + qSj) / M + s_;

    double pMp = p0 * p0 * i00 + p1 * p1 * i11 + p2 * p2 * i22 +
                 2.0 * (p0 * p1 * i01 + p0 * p2 * i02 + p1 * p2 * i12);
    double qMq = q0 * q0 * j00 + q1 * q1 * j11 + q2 * q2 * j22 +
                 2.0 * (q0 * q1 * j01 + q0 * q2 * j02 + q1 * q2 * j12);
    double pMq = p0 * (q0 * S[18] + q1 * S[19] + q2 * S[20]) +
                 p1 * (q0 * S[21] + q1 * S[22] + q2 * S[23]) +
                 p2 * (q0 * S[24] + q1 * S[25] + q2 * S[26]);

    double sumsq = pMp + qMq + 2.0 * pMq + 2.0 * s_ * (pSi + qSj) + M * s_ * s_;
    double var = sumsq / M - mean * mean;
    double rstd = 1.0 / sqrt(var + 1e-5);

    double g = (double)gamma[c];
    g_scale[c] = (float)(g * rstd);
    g_shift[c] = (float)((double)beta[c] - mean * g * rstd);
}

// =============================================================================
// Kernel 4: fused edge-MLP + BN + ReLU + (r @ w2) + max over K.
// One warp per point: 2 output channels per lane. BN applied UNFOLDED
// (h computed with raw w1/b1, then scale/shift) to match reference rounding.
// Stage-2 GEMM uses packed fma.rn.f32x2 (FFMA2).
// =============================================================================
__global__ void __launch_bounds__(256, 3)
main_kernel(const float* __restrict__ x,
            const float* __restrict__ w1,
            const float* __restrict__ b1,
            const float* __restrict__ w2,
            const float* __restrict__ b2,
            float* __restrict__ out) {
    extern __shared__ float sm[];
    float* w2s = sm;               // 64*64
    float* rt  = sm + CO * CO;     // 8 warps * 64 * 20

    for (int i = threadIdx.x; i < CO * CO; i += blockDim.x) w2s[i] = w2[i];
    __syncthreads();

    const int w = threadIdx.x >> 5;
    const int l = threadIdx.x & 31;
    const int pt = blockIdx.x * 8 + w;
    float* rw = rt + w * (CO * K_NN);

    const int ca = l, cb = l + 32;

    float w1a[6], w1b[6];
#pragma unroll
    for (int r = 0; r < 6; r++) {
        w1a[r] = __ldg(w1 + r * CO + ca);
        w1b[r] = __ldg(w1 + r * CO + cb);
    }
    const float b1a = __ldg(b1 + ca), b1b = __ldg(b1 + cb);
    const float sca = g_scale[ca], scb = g_scale[cb];
    const float sha = g_shift[ca], shb = g_shift[cb];

    const int b = pt >> 12;
    const int gbase = b << 12;
    const float* xr = x + (size_t)pt * 3;
    const float xi0 = __ldg(xr), xi1 = __ldg(xr + 1), xi2 = __ldg(xr + 2);
    const int* ip = g_idx + (size_t)pt * K_NN;

    // ---- stage 1: r[c][k] = relu(scale*h + shift) ----
#pragma unroll 4
    for (int k = 0; k < K_NN; k++) {
        int j = __ldg(ip + k);
        const float* xp = x + (size_t)(gbase + j) * 3;
        float d0 = __ldg(xp)     - xi0;
        float d1 = __ldg(xp + 1) - xi1;
        float d2 = __ldg(xp + 2) - xi2;

        float ha = b1a;
        ha = fmaf(xi0, w1a[0], ha); ha = fmaf(xi1, w1a[1], ha); ha = fmaf(xi2, w1a[2], ha);
        ha = fmaf(d0,  w1a[3], ha); ha = fmaf(d1,  w1a[4], ha); ha = fmaf(d2,  w1a[5], ha);
        float hb = b1b;
        hb = fmaf(xi0, w1b[0], hb); hb = fmaf(xi1, w1b[1], hb); hb = fmaf(xi2, w1b[2], hb);
        hb = fmaf(d0,  w1b[3], hb); hb = fmaf(d1,  w1b[4], hb); hb = fmaf(d2,  w1b[5], hb);

        rw[ca * K_NN + k] = fmaxf(fmaf(ha, sca, sha), 0.0f);
        rw[cb * K_NN + k] = fmaxf(fmaf(hb, scb, shb), 0.0f);
    }
    __syncwarp();

    // ---- stage 2: packed FFMA2 GEMM, acc[i] holds k=(2i, 2i+1) ----
    unsigned long long acca[K_NN / 2], accb[K_NN / 2];
#pragma unroll
    for (int i = 0; i < K_NN / 2; i++) { acca[i] = 0ULL; accb[i] = 0ULL; }

#pragma unroll 4
    for (int c = 0; c < CO; c++) {
        float wa = w2s[c * CO + ca];
        float wb = w2s[c * CO + cb];
        unsigned long long wa2 = pack2(wa, wa);
        unsigned long long wb2 = pack2(wb, wb);
        const ulonglong2* r2 = (const ulonglong2*)(rw + c * K_NN);
#pragma unroll
        for (int t = 0; t < 5; t++) {
            ulonglong2 rv = r2[t];
            FMA2(acca[2 * t],     rv.x, wa2, acca[2 * t]);
            FMA2(acca[2 * t + 1], rv.y, wa2, acca[2 * t + 1]);
            FMA2(accb[2 * t],     rv.x, wb2, accb[2 * t]);
            FMA2(accb[2 * t + 1], rv.y, wb2, accb[2 * t + 1]);
        }
    }

    float ma = -3.402823466e38f, mb = -3.402823466e38f;
#pragma unroll
    for (int i = 0; i < K_NN / 2; i++) {
        float a0, a1, b0, b1v;
        unpack2(acca[i], a0, a1);
        unpack2(accb[i], b0, b1v);
        ma = fmaxf(ma, fmaxf(a0, a1));
        mb = fmaxf(mb, fmaxf(b0, b1v));
    }

    out[(size_t)pt * CO + ca] = ma + __ldg(b2 + ca);
    out[(size_t)pt * CO + cb] = mb + __ldg(b2 + cb);
}

// =============================================================================
extern "C" void kernel_launch(void* const* d_in, const int* in_sizes, int n_in,
                              void* d_out, int out_size) {
    const float* x     = (const float*)d_in[0];
    // d_in[1] = batch indices (implied by layout; unused)
    const float* w1    = (const float*)d_in[2];
    const float* b1    = (const float*)d_in[3];
    const float* gamma = (const float*)d_in[4];
    const float* beta  = (const float*)d_in[5];
    const float* w2    = (const float*)d_in[6];
    const float* b2    = (const float*)d_in[7];
    float* out = (float*)d_out;

    const int knn_smem  = N_PTS * sizeof(float4) + 16 * CAP * 256;      // 160 KB
    const int main_smem = (CO * CO + 8 * CO * K_NN) * sizeof(float);    // 56 KB

    cudaFuncSetAttribute(knn_kernel,  cudaFuncAttributeMaxDynamicSharedMemorySize, knn_smem);
    cudaFuncSetAttribute(main_kernel, cudaFuncAttributeMaxDynamicSharedMemorySize, main_smem);

    knn_kernel<<<B_SZ * 8, 512, knn_smem>>>(x);
    stats_kernel<<<STAT_BLOCKS, 256>>>(x);
    finalize_kernel<<<1, 64>>>(w1, b1, gamma, beta);
    main_kernel<<<(B_SZ * N_PTS) / 8, 256, main_smem>>>(x, w1, b1, w2, b2, out);
}